// round 7
// baseline (speedup 1.0000x reference)
#include <cuda_runtime.h>

#define DD 64
#define MAXN 100000
#define MAXE 1000000
typedef unsigned long long u64;

__device__ float g_xa[(size_t)MAXN * DD];
__device__ float g_xb[(size_t)MAXN * DD];
__device__ float g_h1[(size_t)MAXE * DD];
__device__ float g_h2[(size_t)MAXN * DD];
__device__ float g_sums[(size_t)MAXN * DD];
__device__ float g_cnt[MAXN];
__device__ float g_st1[128], g_st2[128], g_ss1[128], g_ss2[128];

__device__ __forceinline__ u64 pk2(float lo, float hi) {
    u64 d; asm("mov.b64 %0, {%1,%2};" : "=l"(d) : "f"(lo), "f"(hi)); return d;
}
__device__ __forceinline__ void fma2(u64& d, u64 a, u64 b) {
    asm("fma.rn.f32x2 %0, %1, %2, %0;" : "+l"(d) : "l"(a), "l"(b));
}
__device__ __forceinline__ float2 up2(u64 d) {
    float2 r; asm("mov.b64 {%0,%1}, %2;" : "=f"(r.x), "=f"(r.y) : "l"(d)); return r;
}
__device__ __forceinline__ float silu_f(float v) {
    return __fdividef(v, 1.0f + __expf(-v));
}

__global__ void zero_all(int N) {
    size_t i = (size_t)blockIdx.x * blockDim.x + threadIdx.x;
    if (i < (size_t)N * DD) g_sums[i] = 0.f;
    if (i < (size_t)N) g_cnt[i] = 0.f;
    if (i < 128) { g_st1[i] = 0.f; g_st2[i] = 0.f; }
}

// Unified tile-64x64 GEMM: C[M,64] = A'[M,64] @ Wsl[64,64] + add, where
// A' = A (or A row-scaled by 1/max(cnt,1) if cnt!=null).
// add = bias[64] broadcast (if addmat==null) else addmat[idx?idx[n]:n].
// If stats!=null, accumulates per-column sum & sumsq of C into stats[0:64|64:128].
__global__ __launch_bounds__(256) void gemm_kernel(
    const float* __restrict__ A, const float* __restrict__ cnt,
    const float* __restrict__ Wsl, const float* __restrict__ bias,
    const float* __restrict__ addmat, const int* __restrict__ idx,
    float* __restrict__ C, float* __restrict__ stats, int M, int tiles)
{
    __shared__ u64   sAd[64 * 64];   // 32 KB, (a,a) duplicated pairs
    __shared__ float sW [64 * 64];   // 16 KB
    int tid = threadIdx.x;
    int tx = tid & 15, ty = tid >> 4;
    int j0 = tx * 4, e0 = ty * 4;
    for (int i = tid; i < 4096; i += 256) sW[i] = Wsl[i];

    float ps[4] = {0,0,0,0}, pq[4] = {0,0,0,0};

    for (int t = blockIdx.x; t < tiles; t += gridDim.x) {
        int base = t * 64;
        __syncthreads();
        {
            const float4* src = (const float4*)A + (size_t)base * 16;
            #pragma unroll
            for (int i = tid; i < 1024; i += 256) {
                int r = base + (i >> 4);
                float4 v = make_float4(0.f, 0.f, 0.f, 0.f);
                if (r < M) {
                    v = src[i];
                    if (cnt) {
                        float inv = __fdividef(1.0f, fmaxf(cnt[r], 1.0f));
                        v.x *= inv; v.y *= inv; v.z *= inv; v.w *= inv;
                    }
                }
                u64* d = &sAd[(size_t)(i >> 4) * 64 + (i & 15) * 4];
                d[0] = pk2(v.x, v.x); d[1] = pk2(v.y, v.y);
                d[2] = pk2(v.z, v.z); d[3] = pk2(v.w, v.w);
            }
        }
        __syncthreads();
        u64 acc[8];
        #pragma unroll
        for (int i = 0; i < 8; i++) acc[i] = 0ull;
        #pragma unroll 16
        for (int k = 0; k < 64; k++) {
            u64 a0 = sAd[(e0 + 0) * 64 + k];
            u64 a1 = sAd[(e0 + 1) * 64 + k];
            u64 a2 = sAd[(e0 + 2) * 64 + k];
            u64 a3 = sAd[(e0 + 3) * 64 + k];
            u64 w01 = *(const u64*)&sW[k * 64 + j0];
            u64 w23 = *(const u64*)&sW[k * 64 + j0 + 2];
            fma2(acc[0], a0, w01); fma2(acc[1], a0, w23);
            fma2(acc[2], a1, w01); fma2(acc[3], a1, w23);
            fma2(acc[4], a2, w01); fma2(acc[5], a2, w23);
            fma2(acc[6], a3, w01); fma2(acc[7], a3, w23);
        }
        #pragma unroll
        for (int s = 0; s < 4; s++) {
            int n = base + e0 + s;
            if (n < M) {
                float4 av;
                if (addmat) {
                    int r2 = idx ? idx[n] : n;
                    av = *(const float4*)(addmat + (size_t)r2 * 64 + j0);
                } else {
                    av = *(const float4*)(bias + j0);
                }
                float2 ha = up2(acc[s * 2]);
                float2 hb = up2(acc[s * 2 + 1]);
                float4 o = make_float4(ha.x + av.x, ha.y + av.y, hb.x + av.z, hb.y + av.w);
                *((float4*)C + (size_t)n * 16 + tx) = o;
                ps[0] += o.x; pq[0] += o.x * o.x;
                ps[1] += o.y; pq[1] += o.y * o.y;
                ps[2] += o.z; pq[2] += o.z * o.z;
                ps[3] += o.w; pq[3] += o.w * o.w;
            }
        }
    }
    if (!stats) return;
    __syncthreads();
    float* sred = sW;   // reuse as 16x128 scratch
    #pragma unroll
    for (int jj = 0; jj < 4; jj++) {
        sred[ty * 128 + tx * 8 + jj]     = ps[jj];
        sred[ty * 128 + tx * 8 + 4 + jj] = pq[jj];
    }
    __syncthreads();
    if (tid < 128) {
        float v = 0.f;
        #pragma unroll
        for (int r = 0; r < 16; r++) v += sred[r * 128 + tid];
        int jj = tid & 3, sq = (tid >> 2) & 1, g = tid >> 3;
        atomicAdd(&stats[sq * 64 + g * 4 + jj], v);
    }
}

__global__ void finalize_kernel(const float* __restrict__ st,
                                const float* __restrict__ g,
                                const float* __restrict__ be,
                                float* __restrict__ ss, float invM)
{
    int j = threadIdx.x;
    if (j < 64) {
        float mu  = st[j] * invM;
        float var = fmaxf(st[64 + j] * invM - mu * mu, 0.f);
        float sc  = g[j] * rsqrtf(var + 1e-5f);
        ss[j]      = sc;
        ss[64 + j] = fmaf(-mu, sc, be[j]);
    }
}

// BN1+SiLU on h1, 128-bit vector atomic scatter-add + count
__global__ __launch_bounds__(256) void scatter_kernel(
    const float4* __restrict__ H1, const int* __restrict__ colIdx,
    const float* __restrict__ ss, float4* __restrict__ sums,
    float* __restrict__ cnt, int E)
{
    __shared__ int scol[16];
    int ge0 = blockIdx.x * 16;
    int tid = threadIdx.x;
    if (tid < 16) { int ge = ge0 + tid; scol[tid] = (ge < E) ? colIdx[ge] : 0; }
    __syncthreads();
    int el = tid >> 4, q = tid & 15;
    int ge = ge0 + el;
    if (ge < E) {
        float4 h  = H1[(size_t)ge * 16 + q];
        float4 sc = *(const float4*)(ss + q * 4);
        float4 sh = *(const float4*)(ss + 64 + q * 4);
        float4 y;
        y.x = silu_f(fmaf(h.x, sc.x, sh.x));
        y.y = silu_f(fmaf(h.y, sc.y, sh.y));
        y.z = silu_f(fmaf(h.z, sc.z, sh.z));
        y.w = silu_f(fmaf(h.w, sc.w, sh.w));
        int c = scol[el];
        atomicAdd(&sums[(size_t)c * 16 + q], y);
        if (q == 0) atomicAdd(&cnt[c], 1.0f);
    }
}

__global__ void bn_silu_out(const float4* __restrict__ H2,
                            const float* __restrict__ ss,
                            float4* __restrict__ out, int n4)
{
    int i = blockIdx.x * blockDim.x + threadIdx.x;
    if (i < n4) {
        int q = i & 15;
        float4 h  = H2[i];
        float4 sc = *(const float4*)(ss + q * 4);
        float4 sh = *(const float4*)(ss + 64 + q * 4);
        float4 y;
        y.x = silu_f(fmaf(h.x, sc.x, sh.x));
        y.y = silu_f(fmaf(h.y, sc.y, sh.y));
        y.z = silu_f(fmaf(h.z, sc.z, sh.z));
        y.w = silu_f(fmaf(h.w, sc.w, sh.w));
        out[i] = y;
    }
}

extern "C" void kernel_launch(void* const* d_in, const int* in_sizes, int n_in,
                              void* d_out, int out_size)
{
    if (n_in < 12) return;
    const float* x   = (const float*)d_in[0];
    const float* ea  = (const float*)d_in[1];
    const float* W1  = (const float*)d_in[3];
    const float* b1  = (const float*)d_in[4];
    const float* g1  = (const float*)d_in[5];
    const float* be1 = (const float*)d_in[6];
    const float* W2  = (const float*)d_in[7];
    const float* b2  = (const float*)d_in[8];
    const float* g2  = (const float*)d_in[9];
    const float* be2 = (const float*)d_in[10];
    const int*   ei  = (const int*)d_in[11];   // int32 (jax x64 disabled)

    int N = in_sizes[0] / DD;
    int E = in_sizes[1] / DD;
    if (N <= 0 || E <= 0 || N > MAXN || E > MAXE) return;

    void *p0, *p1, *p2, *p3, *p4, *p5, *p6, *p7, *p8, *p9;
    cudaGetSymbolAddress(&p0, g_xa);   cudaGetSymbolAddress(&p1, g_xb);
    cudaGetSymbolAddress(&p2, g_h1);   cudaGetSymbolAddress(&p3, g_h2);
    cudaGetSymbolAddress(&p4, g_sums); cudaGetSymbolAddress(&p5, g_cnt);
    cudaGetSymbolAddress(&p6, g_st1);  cudaGetSymbolAddress(&p7, g_st2);
    cudaGetSymbolAddress(&p8, g_ss1);  cudaGetSymbolAddress(&p9, g_ss2);
    float *xa = (float*)p0, *xb = (float*)p1, *h1 = (float*)p2, *h2 = (float*)p3;
    float *sums = (float*)p4, *cnt = (float*)p5;
    float *st1 = (float*)p6, *st2 = (float*)p7, *ss1 = (float*)p8, *ss2 = (float*)p9;

    int tilesN = (N + 63) / 64;
    int tilesE = (E + 63) / 64;
    int zb = (int)(((size_t)N * DD + 255) / 256);
    const int G = 592;   // 148 SM x 4 blocks (48KB smem each)

    zero_all<<<zb, 256>>>(N);
    // xa = x @ W1[0:64] + b1 ; xb = x @ W2[0:64] + b2
    gemm_kernel<<<G, 256>>>(x, nullptr, W1, b1, nullptr, nullptr, xa, nullptr, N, tilesN);
    gemm_kernel<<<G, 256>>>(x, nullptr, W2, b2, nullptr, nullptr, xb, nullptr, N, tilesN);
    // h1 = ea @ W1[64:128] + xa[row]  (+ batch stats)
    gemm_kernel<<<G, 256>>>(ea, nullptr, W1 + 4096, nullptr, xa, ei, h1, st1, E, tilesE);
    finalize_kernel<<<1, 64>>>(st1, g1, be1, ss1, 1.0f / (float)E);
    // silu(bn(h1)) scatter-add into sums/cnt by col
    scatter_kernel<<<(E + 15) / 16, 256>>>((const float4*)h1, ei + E, ss1,
                                           (float4*)sums, cnt, E);
    // h2 = (sums/max(cnt,1)) @ W2[64:128] + xb  (+ batch stats)
    gemm_kernel<<<G, 256>>>(sums, cnt, W2 + 4096, nullptr, xb, nullptr, h2, st2, N, tilesN);
    finalize_kernel<<<1, 64>>>(st2, g2, be2, ss2, 1.0f / (float)N);
    // out = silu(bn(h2))
    bn_silu_out<<<(N * 16 + 255) / 256, 256>>>((const float4*)h2, ss2,
                                               (float4*)d_out, N * 16);
}